// round 16
// baseline (speedup 1.0000x reference)
#include <cuda_runtime.h>

// Static device scratch (no allocation allowed anywhere). Zero at module
// load; each finalizer atomicExch's its accum columns back to 0 and resets
// its counter, so every invocation (incl. graph replays) starts clean.
#define MAX_SEGS 8192
#define HMAX     2

__device__ float g_accum[MAX_SEGS * 256];        // 8 MB
__device__ int   g_cnt[MAX_SEGS * HMAX];         // per (segment, col-half)

__device__ __forceinline__ int load_seg(const void* batch, int is64, int idx) {
    return is64 ? (int)((const long long*)batch)[idx]
                : ((const int*)batch)[idx];
}

// Warp-collective lower_bound: smallest i in [0,n] with batch[i] >= target.
__device__ __forceinline__ int warp_lower_bound(const void* batch, int is64,
                                                int n, int target, int lane) {
    int lo = 0, hi = n;
    while (hi - lo > 32) {
        int chunk = (hi - lo + 31) >> 5;          // ceil(range/32)
        int idx   = lo + lane * chunk;
        bool lt   = false;
        if (idx < hi) lt = load_seg(batch, is64, idx) < target;
        unsigned bal = __ballot_sync(0xFFFFFFFFu, lt);
        if (bal == 0) { hi = lo; break; }
        int l     = 31 - __clz(bal);
        int newlo = lo + l * chunk + 1;
        int newhi = lo + (l + 1) * chunk;
        hi = newhi < hi ? newhi : hi;
        lo = newlo;
    }
    if (hi <= lo) return lo;
    bool ge = false;
    int idx = lo + lane;
    if (idx < hi) ge = load_seg(batch, is64, idx) >= target;
    unsigned bal = __ballot_sync(0xFFFFFFFFu, ge);
    return bal ? (lo + __ffs(bal) - 1) : hi;
}

__device__ __forceinline__ void acc4(float4 v, float a[4]) {
    a[0] += __expf(v.x);
    a[1] += __expf(v.y);
    a[2] += __expf(v.z);
    a[3] += __expf(v.w);
}

// ---------------------------------------------------------------------------
// One block per (segment, 128-col half, row-half). 128 threads = 32 float4-
// lanes x 4 row-groups — the champion R15 block shape and hot loop, verbatim.
// Grid 2048 = 1.73x oversubscription: HW scheduler back-fills finished slots
// (dynamic balancing); wave-2 startup hides under other blocks' streaming.
// Two-contributor atomic merge per (segment, col-half); second arriver
// finalizes (log+store) and resets scratch. Empty segments: both halves add
// 0, finalizer writes log(1e-12) — no special casing.
// ---------------------------------------------------------------------------
__global__ __launch_bounds__(128, 8)
void pool_lse_kernel(const float* __restrict__ feats,
                     const void* __restrict__ batch,
                     float* __restrict__ out,
                     int n, int D, int G) {
    __shared__ int sh_is64;
    __shared__ int sh_bounds[2];
    __shared__ int sh_fin;

    const int lane = threadIdx.x & 31;
    const int rg   = threadIdx.x >> 5;            // warp / row-group 0..3

    // Dtype probe (warp 0): int64 values in [0,G) => odd 32-bit words are all
    // zero high-halves; any nonzero sampled odd word => int32.
    if (rg == 0) {
        const int* b32 = (const int*)batch;
        int limit = n < 8192 ? n : 8192;
        int step  = limit / 32; if (step < 2) step = 2;
        int idx   = lane * step + 1;
        if (idx >= limit) idx = limit - 1;
        idx |= 1;
        if (idx >= limit) idx -= 2;
        int v = (idx >= 0) ? b32[idx] : 0;
        unsigned nz = __ballot_sync(0xFFFFFFFFu, v != 0);
        if (lane == 0) sh_is64 = (nz == 0) ? 1 : 0;
    }
    __syncthreads();
    const int is64 = sh_is64;

    const int g = blockIdx.x;

    // Warps 0/1: lower_bound(g) / lower_bound(g+1), ~5 L2-resident loads.
    if (rg < 2) {
        int r = warp_lower_bound(batch, is64, n, g + rg, lane);
        if (lane == 0) sh_bounds[rg] = r;
    }
    __syncthreads();

    const int start = sh_bounds[0];
    const int end   = sh_bounds[1];
    const int mid   = start + ((end - start) >> 1);
    const int z     = blockIdx.z;                 // row half
    const int rs    = z ? mid : start;
    const int re    = z ? end : mid;

    const int h      = blockIdx.y;
    const int colblk = h * 128;
    const int c4     = (colblk >> 2) + lane;

    float s[4] = {0.f, 0.f, 0.f, 0.f};
    float t[4] = {0.f, 0.f, 0.f, 0.f};

    const size_t rstride = (size_t)(D >> 2);      // float4s per row
    const float4* __restrict__ p =
        (const float4*)feats + (size_t)(rs + rg) * rstride + c4;

    int r = rs + rg;                              // rows: r, r+4, r+8, ...
    if (r + 12 < re) {
        // Prologue: 4 in-flight streaming LDG.128.
        float4 a0 = __ldcs(p);
        float4 a1 = __ldcs(p +  4 * rstride);
        float4 a2 = __ldcs(p +  8 * rstride);
        float4 a3 = __ldcs(p + 12 * rstride);
        p += 16 * rstride;
        r += 16;
        // Steady state: explicit role swap, no register moves.
        for (;;) {
            if (r + 12 >= re) {
                acc4(a0, s); acc4(a1, t); acc4(a2, s); acc4(a3, t);
                break;
            }
            float4 b0 = __ldcs(p);
            float4 b1 = __ldcs(p +  4 * rstride);
            float4 b2 = __ldcs(p +  8 * rstride);
            float4 b3 = __ldcs(p + 12 * rstride);
            p += 16 * rstride;
            r += 16;
            acc4(a0, s); acc4(a1, t); acc4(a2, s); acc4(a3, t);

            if (r + 12 >= re) {
                acc4(b0, s); acc4(b1, t); acc4(b2, s); acc4(b3, t);
                break;
            }
            a0 = __ldcs(p);
            a1 = __ldcs(p +  4 * rstride);
            a2 = __ldcs(p +  8 * rstride);
            a3 = __ldcs(p + 12 * rstride);
            p += 16 * rstride;
            r += 16;
            acc4(b0, s); acc4(b1, t); acc4(b2, s); acc4(b3, t);
        }
    }
    for (; r < re; r += 4) {
        float4 v = __ldcs(p);
        p += 4 * rstride;
        acc4(v, s);
    }

    // ---- merge 4 row-group partials per column through shared memory ----
    __shared__ float sm_s[4][128];
#pragma unroll
    for (int j = 0; j < 4; ++j) {
        sm_s[rg][lane * 4 + j] = s[j] + t[j];
    }
    __syncthreads();

    const int c = threadIdx.x;                    // 128 threads = 128 columns
    const float S = sm_s[0][c] + sm_s[1][c] + sm_s[2][c] + sm_s[3][c];

    // ---- two-contributor merge: second arriver finalizes ----
    atomicAdd(&g_accum[(size_t)g * D + colblk + c], S);
    __threadfence();                  // release: our adds visible before count
    __syncthreads();
    if (threadIdx.x == 0) {
        int old = atomicAdd(&g_cnt[g * HMAX + h], 1);
        sh_fin = (old == 1) ? 1 : 0;
    }
    __syncthreads();
    if (sh_fin) {
        __threadfence();              // acquire: see sibling's adds
        float v = atomicExch(&g_accum[(size_t)g * D + colblk + c], 0.0f);
        out[(size_t)g * D + colblk + c] = __logf(fmaxf(v, 1e-12f));
        if (threadIdx.x == 0) atomicExch(&g_cnt[g * HMAX + h], 0);
    }
}

// ---------------------------------------------------------------------------
// Inputs (metadata order): feats f32 [N*D], batch int [N], num_segments.
// ---------------------------------------------------------------------------
extern "C" void kernel_launch(void* const* d_in, const int* in_sizes, int n_in,
                              void* d_out, int out_size) {
    const float* feats = (const float*)d_in[0];
    const void*  batch = d_in[1];

    const int n = in_sizes[1];                // rows (200000)
    const int D = in_sizes[0] / n;            // features (256)
    const int G = out_size / D;               // segments (512)

    dim3 grid(G, D / 128, 2);                 // (segment, col-half, row-half)
    pool_lse_kernel<<<grid, 128>>>(feats, batch, (float*)d_out, n, D, G);
}